// round 10
// baseline (speedup 1.0000x reference)
#include <cuda_runtime.h>
#include <cuda_fp16.h>
#include <cuda_bf16.h>
#include <cstdint>

#define BB 64
#define TT 2048
#define DD 512
#define UU 512

// ---------------- device scratch (no cudaMalloc allowed) ----------------
__device__ float g_hb[BB * UU];                 // h_proj + W1_b
__device__ float g_lpart[4][BB * TT];           // logits partials per u-slice
__device__ float g_part[BB][32][2][DD];         // context partials
__device__ __half g_W1f[UU * DD];               // W1^T fp16  [u][k]

// ---------------- helpers ----------------
__device__ __forceinline__ uint32_t smem_u32(const void* p) {
    uint32_t a;
    asm("{ .reg .u64 t; cvta.to.shared.u64 t, %1; cvt.u32.u64 %0, t; }" : "=r"(a) : "l"(p));
    return a;
}
__device__ __forceinline__ float tanh_fast(float x) {
    float y; asm("tanh.approx.f32 %0, %1;" : "=f"(y) : "f"(x)); return y;
}
__device__ __forceinline__ void cp16(uint32_t dst, const void* src) {
    asm volatile("cp.async.cg.shared.global [%0], [%1], 16;" :: "r"(dst), "l"(src) : "memory");
}
__device__ __forceinline__ void ldsm4(uint32_t* r, uint32_t addr) {
    asm volatile("ldmatrix.sync.aligned.m8n8.x4.shared.b16 {%0,%1,%2,%3}, [%4];"
                 : "=r"(r[0]), "=r"(r[1]), "=r"(r[2]), "=r"(r[3]) : "r"(addr));
}
__device__ __forceinline__ void mma_f16(float* c, const uint32_t* a, const uint32_t* b) {
    asm volatile("mma.sync.aligned.m16n8k16.row.col.f32.f16.f16.f32 "
                 "{%0,%1,%2,%3}, {%4,%5,%6,%7}, {%8,%9}, {%0,%1,%2,%3};"
                 : "+f"(c[0]), "+f"(c[1]), "+f"(c[2]), "+f"(c[3])
                 : "r"(a[0]), "r"(a[1]), "r"(a[2]), "r"(a[3]), "r"(b[0]), "r"(b[1]));
}

// ---------------------------------------------------------------------------
// k_prepw: W1 [k][u] -> W1^T fp16 [u][k]
// ---------------------------------------------------------------------------
__global__ __launch_bounds__(512) void k_prepw(const float* __restrict__ W1) {
    int u = blockIdx.x, k = threadIdx.x;
    g_W1f[(size_t)u * DD + k] = __float2half_rn(W1[(size_t)k * UU + u]);
}

// ---------------------------------------------------------------------------
// k_hproj: g_hb[b,u] = hidden[b,:] @ W2[:,u] + W2_b[u] + W1_b[u]
// ---------------------------------------------------------------------------
__global__ __launch_bounds__(512) void k_hproj(
    const float* __restrict__ hidden, const float* __restrict__ W2,
    const float* __restrict__ W2b, const float* __restrict__ W1b)
{
    int b = blockIdx.x, u = threadIdx.x;
    __shared__ float h[DD];
    h[u] = hidden[b * DD + u];
    __syncthreads();
    float a0 = 0.f, a1 = 0.f, a2 = 0.f, a3 = 0.f;
    #pragma unroll 4
    for (int k = 0; k < DD; k += 4) {
        a0 = fmaf(h[k + 0], W2[(k + 0) * UU + u], a0);
        a1 = fmaf(h[k + 1], W2[(k + 1) * UU + u], a1);
        a2 = fmaf(h[k + 2], W2[(k + 2) * UU + u], a2);
        a3 = fmaf(h[k + 3], W2[(k + 3) * UU + u], a3);
    }
    g_hb[b * UU + u] = ((a0 + a1) + (a2 + a3)) + W2b[u] + W1b[u];
}

// ---------------------------------------------------------------------------
// k_logits: mma.sync fp16 GEMM, BM=256, 512 threads, + fused tanh/v epilogue.
// ---------------------------------------------------------------------------
#define OFF_A(s)  ((s) * 20480)
#define OFF_B(s)  (40960 + (s) * 10240)
#define OFF_GS 61440
#define OFF_VS 61952
#define OFF_RED 62464
#define SMEM_BYTES 71680

__global__ __launch_bounds__(512, 1)
void k_logits(const float* __restrict__ F, const float* __restrict__ V)
{
    extern __shared__ __align__(128) uint8_t smem[];
    const uint32_t sb = smem_u32(smem);
    const int tid = threadIdx.x;
    const int lane = tid & 31, wid = tid >> 5;
    const int warp_m = wid & 7, warp_n = wid >> 3;   // 8 x 2 warps -> 256 x 128
    const int us = blockIdx.x;                        // u-slice fastest: L2 A-sharing
    const int m0 = blockIdx.y * 256;
    const int b  = m0 >> 11;

    float* gs  = (float*)(smem + OFF_GS);
    float* vsm = (float*)(smem + OFF_VS);
    if (tid < 128) {
        gs[tid]  = g_hb[b * UU + us * 128 + tid];
        vsm[tid] = V[us * 128 + tid];
    }

    const int arow = tid >> 1, ah = tid & 1;          // A: 256 rows, 2 half-rows
    const int brow = tid >> 2, bh = tid & 3;          // B: 128 rows, 4 chunks

    auto cpB = [&](int kt, int buf) {
        const __half* s = g_W1f + (size_t)(us * 128 + brow) * DD + kt * 32 + bh * 8;
        cp16(sb + OFF_B(buf) + (uint32_t)(brow * 80 + bh * 16), s);
    };
    auto ldA = [&](int kt, float4* fr) {
        const float4* p = (const float4*)(F + (size_t)(m0 + arow) * DD + kt * 32 + ah * 16);
        fr[0] = p[0]; fr[1] = p[1]; fr[2] = p[2]; fr[3] = p[3];
    };
    auto stA = [&](const float4* fr, int buf) {
        float x[16] = {fr[0].x, fr[0].y, fr[0].z, fr[0].w, fr[1].x, fr[1].y, fr[1].z, fr[1].w,
                       fr[2].x, fr[2].y, fr[2].z, fr[2].w, fr[3].x, fr[3].y, fr[3].z, fr[3].w};
        uint32_t hw[8];
        #pragma unroll
        for (int i = 0; i < 8; i++) {
            __half hA = __float2half_rn(x[2 * i]), hC = __float2half_rn(x[2 * i + 1]);
            hw[i] = (uint32_t)__half_as_ushort(hA) | ((uint32_t)__half_as_ushort(hC) << 16);
        }
        uint32_t d = (uint32_t)(arow * 80 + ah * 32);
        *(uint4*)(smem + OFF_A(buf) + d)      = make_uint4(hw[0], hw[1], hw[2], hw[3]);
        *(uint4*)(smem + OFF_A(buf) + d + 16) = make_uint4(hw[4], hw[5], hw[6], hw[7]);
    };

    float acc[2][8][4];
    #pragma unroll
    for (int i = 0; i < 2; i++)
        #pragma unroll
        for (int j = 0; j < 8; j++)
            #pragma unroll
            for (int q = 0; q < 4; q++) acc[i][j][q] = 0.f;

    float4 fr[4];
    cpB(0, 0); asm volatile("cp.async.commit_group;" ::: "memory");
    cpB(1, 1); asm volatile("cp.async.commit_group;" ::: "memory");
    ldA(0, fr); stA(fr, 0);
    ldA(1, fr);
    asm volatile("cp.async.wait_group 1;" ::: "memory");
    __syncthreads();

    #pragma unroll 1
    for (int t = 0; t < 16; t++) {
        const int buf = t & 1;
        const uint32_t ab = sb + OFF_A(buf);
        const uint32_t bb = sb + OFF_B(buf);
        #pragma unroll
        for (int ks = 0; ks < 2; ks++) {
            const uint32_t kb = ks * 32;
            uint32_t Ah[2][4], Bv[4][4];
            #pragma unroll
            for (int mt = 0; mt < 2; mt++) {
                uint32_t ro = (uint32_t)(warp_m * 32 + mt * 16 + (lane & 15)) * 80 + kb + ((lane >> 4) << 4);
                ldsm4(Ah[mt], ab + ro);
            }
            #pragma unroll
            for (int p = 0; p < 4; p++) {
                uint32_t bo = (uint32_t)(warp_n * 64 + p * 16 + ((lane >> 4) << 3) + (lane & 7)) * 80
                              + kb + (((lane >> 3) & 1) << 4);
                ldsm4(Bv[p], bb + bo);
            }
            #pragma unroll
            for (int mt = 0; mt < 2; mt++)
                #pragma unroll
                for (int p = 0; p < 4; p++) {
                    mma_f16(acc[mt][2 * p],     Ah[mt], &Bv[p][0]);
                    mma_f16(acc[mt][2 * p + 1], Ah[mt], &Bv[p][2]);
                }
        }
        if (t == 15) break;
        __syncthreads();
        stA(fr, (t + 1) & 1);
        if (t + 2 < 16) {
            ldA(t + 2, fr);
            cpB(t + 2, buf);
            asm volatile("cp.async.commit_group;" ::: "memory");
            asm volatile("cp.async.wait_group 1;" ::: "memory");
        } else {
            asm volatile("cp.async.wait_group 0;" ::: "memory");
        }
        __syncthreads();
    }

    // epilogue: partial logits over this u-slice
    float* red = (float*)(smem + OFF_RED);
    #pragma unroll
    for (int mt = 0; mt < 2; mt++)
        #pragma unroll
        for (int hf = 0; hf < 2; hf++) {
            float p = 0.f;
            #pragma unroll
            for (int nt = 0; nt < 8; nt++) {
                int u = warp_n * 64 + nt * 8 + (lane & 3) * 2;
                p += tanh_fast(acc[mt][nt][hf * 2 + 0] + gs[u])     * vsm[u];
                p += tanh_fast(acc[mt][nt][hf * 2 + 1] + gs[u + 1]) * vsm[u + 1];
            }
            int ml = warp_m * 32 + mt * 16 + hf * 8 + (lane >> 2);
            red[ml * 9 + warp_n * 4 + (lane & 3)] = p;
        }
    __syncthreads();
    if (tid < 256) {
        float s = 0.f;
        #pragma unroll
        for (int i = 0; i < 8; i++) s += red[tid * 9 + i];
        g_lpart[us][m0 + tid] = s;
    }
}

// ---------------------------------------------------------------------------
// k_softmax: sum u-slice partials, softmax over T
// ---------------------------------------------------------------------------
__global__ __launch_bounds__(256) void k_softmax(float* __restrict__ out_w)
{
    int b = blockIdx.x, tid = threadIdx.x;
    __shared__ float smax[8], ssum[8];
    float v[8];
    float mx = -1e30f;
    #pragma unroll
    for (int i = 0; i < 8; i++) {
        int idx = b * TT + tid + i * 256;
        v[i] = g_lpart[0][idx] + g_lpart[1][idx] + g_lpart[2][idx] + g_lpart[3][idx];
        mx = fmaxf(mx, v[i]);
    }
    #pragma unroll
    for (int o = 16; o > 0; o >>= 1) mx = fmaxf(mx, __shfl_xor_sync(~0u, mx, o));
    if ((tid & 31) == 0) smax[tid >> 5] = mx;
    __syncthreads();
    mx = smax[0];
    #pragma unroll
    for (int i = 1; i < 8; i++) mx = fmaxf(mx, smax[i]);
    float s = 0.f;
    #pragma unroll
    for (int i = 0; i < 8; i++) { v[i] = expf(v[i] - mx); s += v[i]; }
    #pragma unroll
    for (int o = 16; o > 0; o >>= 1) s += __shfl_xor_sync(~0u, s, o);
    if ((tid & 31) == 0) ssum[tid >> 5] = s;
    __syncthreads();
    s = ssum[0];
    #pragma unroll
    for (int i = 1; i < 8; i++) s += ssum[i];
    float inv = 1.f / s;
    #pragma unroll
    for (int i = 0; i < 8; i++) out_w[b * TT + tid + i * 256] = v[i] * inv;
}

// ---------------------------------------------------------------------------
// k_ctx_part / k_ctx_red: context = sum_t w * F, two-stage deterministic
// ---------------------------------------------------------------------------
__global__ __launch_bounds__(256) void k_ctx_part(
    const float* __restrict__ F, const float* __restrict__ w)
{
    int tc = blockIdx.x, b = blockIdx.y, tid = threadIdx.x;
    __shared__ float ws[64];
    if (tid < 64) ws[tid] = w[b * TT + tc * 64 + tid];
    __syncthreads();
    int q = tid & 127, r2 = tid >> 7;
    const float4* F4 = (const float4*)(F + ((size_t)b * TT + (size_t)tc * 64) * DD) + q;
    float ax = 0.f, ay = 0.f, az = 0.f, aw = 0.f;
    #pragma unroll 8
    for (int i = 0; i < 32; i++) {
        int t = r2 + 2 * i;
        float wv = ws[t];
        float4 v = F4[(size_t)t * 128];
        ax = fmaf(wv, v.x, ax); ay = fmaf(wv, v.y, ay);
        az = fmaf(wv, v.z, az); aw = fmaf(wv, v.w, aw);
    }
    float4 o; o.x = ax; o.y = ay; o.z = az; o.w = aw;
    ((float4*)&g_part[b][tc][r2][0])[q] = o;
}

__global__ __launch_bounds__(512) void k_ctx_red(float* __restrict__ out_c)
{
    int b = blockIdx.x, d = threadIdx.x;
    float s = 0.f;
    const float* p = &g_part[b][0][0][0];
    #pragma unroll
    for (int i = 0; i < 64; i++) s += p[i * DD + d];
    out_c[b * DD + d] = s;
}

// ---------------------------------------------------------------------------
extern "C" void kernel_launch(void* const* d_in, const int* in_sizes, int n_in,
                              void* d_out, int out_size)
{
    const float* features = (const float*)d_in[0];
    const float* hidden   = (const float*)d_in[1];
    const float* W1_w     = (const float*)d_in[2];
    const float* W1_b     = (const float*)d_in[3];
    const float* W2_w     = (const float*)d_in[4];
    const float* W2_b     = (const float*)d_in[5];
    const float* V_w      = (const float*)d_in[6];
    // V_b cancels in softmax

    float* out   = (float*)d_out;
    float* out_c = out;               // [B, D]
    float* out_w = out + BB * DD;     // [B, T, 1]

    cudaFuncSetAttribute(k_logits, cudaFuncAttributeMaxDynamicSharedMemorySize, SMEM_BYTES);

    k_prepw  <<<512, 512>>>(W1_w);
    k_hproj  <<<BB, 512>>>(hidden, W2_w, W2_b, W1_b);
    k_logits <<<dim3(4, 512), 512, SMEM_BYTES>>>(features, V_w);
    k_softmax<<<BB, 256>>>(out_w);
    k_ctx_part<<<dim3(32, BB), 256>>>(features, out_w);
    k_ctx_red<<<BB, 512>>>(out_c);
}